// round 4
// baseline (speedup 1.0000x reference)
#include <cuda_runtime.h>

#define N_NODES 50000
#define N_EDGES 800000
#define D 128
#define NBATCH 64

// Scratch (device globals: allocation-free per harness rules)
__device__ float g_agg[N_NODES * D];   // 25.6 MB: (1+eps)*x then += neighbor sum
__device__ float g_S[NBATCH * D];      // per-batch sum of relu'd rows
__device__ float g_cnt[NBATCH];        // per-batch node counts (as float)

// ---------------------------------------------------------------------------
// Kernel 1: agg = (1+eps) * x  (vectorized), and zero the pooling accumulators
// ---------------------------------------------------------------------------
__global__ void k_init(const float* __restrict__ x, const float* __restrict__ eps) {
    int i = blockIdx.x * blockDim.x + threadIdx.x;
    const int total4 = N_NODES * D / 4;
    float scale = 1.0f + eps[0];
    if (i < total4) {
        float4 v = reinterpret_cast<const float4*>(x)[i];
        v.x *= scale; v.y *= scale; v.z *= scale; v.w *= scale;
        reinterpret_cast<float4*>(g_agg)[i] = v;
    }
    if (i < NBATCH * D) g_S[i] = 0.0f;
    if (i < NBATCH)     g_cnt[i] = 0.0f;
}

// ---------------------------------------------------------------------------
// Kernel 2: edge scatter. One warp per edge; each lane moves a float4.
// edge_index is int32 (JAX default x64-disabled downcasts int64 -> int32).
// ---------------------------------------------------------------------------
__global__ void k_edges(const float* __restrict__ x,
                        const int* __restrict__ ei) {
    int warp = (blockIdx.x * blockDim.x + threadIdx.x) >> 5;
    int lane = threadIdx.x & 31;
    if (warp >= N_EDGES) return;
    int src = __ldg(&ei[warp]);
    int dst = __ldg(&ei[N_EDGES + warp]);

    const float4* xs = reinterpret_cast<const float4*>(x + (size_t)src * D);
    float4 v = xs[lane];

    float* p = g_agg + (size_t)dst * D + lane * 4;
    asm volatile("red.global.add.v4.f32 [%0], {%1, %2, %3, %4};"
                 :: "l"(p), "f"(v.x), "f"(v.y), "f"(v.z), "f"(v.w)
                 : "memory");
}

// ---------------------------------------------------------------------------
// Kernel 3: out = relu(agg) written to d_out, fused with per-batch row sums.
// batch is sorted, so run-length compress: accumulate in a register and flush
// to g_S with an atomic only when the batch id changes.
// blockDim = (128, 4): threadIdx.x = feature column, threadIdx.y = row lane.
// ---------------------------------------------------------------------------
#define ROWS_PER_BLOCK 128

__global__ void k_epilogue(float* __restrict__ out,
                           const int* __restrict__ batch) {
    int d = threadIdx.x;
    int rowBase = blockIdx.x * ROWS_PER_BLOCK;
    int rowEnd = rowBase + ROWS_PER_BLOCK;
    if (rowEnd > N_NODES) rowEnd = N_NODES;

    float acc = 0.0f;
    float cntAcc = 0.0f;
    int cur = -1;

    for (int r = rowBase + threadIdx.y; r < rowEnd; r += 4) {
        float v = g_agg[(size_t)r * D + d];
        v = fmaxf(v, 0.0f);
        out[(size_t)r * D + d] = v;

        int b = batch[r];   // same address across the 128 x-threads: broadcast
        if (b != cur) {
            if (cur >= 0) {
                atomicAdd(&g_S[cur * D + d], acc);
                if (d == 0) atomicAdd(&g_cnt[cur], cntAcc);
            }
            cur = b;
            acc = 0.0f;
            cntAcc = 0.0f;
        }
        acc += v;
        cntAcc += 1.0f;
    }
    if (cur >= 0) {
        atomicAdd(&g_S[cur * D + d], acc);
        if (d == 0) atomicAdd(&g_cnt[cur], cntAcc);
    }
}

// ---------------------------------------------------------------------------
// Kernel 4: pooled2[b] = S[b] @ W + cnt[b] * bias   (64x128x128 GEMM: tiny)
// One block per batch row; thread j owns output column j.
// ---------------------------------------------------------------------------
__global__ void k_pool(const float* __restrict__ W,
                       const float* __restrict__ bias,
                       float* __restrict__ out2) {
    int b = blockIdx.x;     // 0..63
    int j = threadIdx.x;    // 0..127
    __shared__ float s[D];
    s[j] = g_S[b * D + j];
    __syncthreads();

    float acc = g_cnt[b] * bias[j];
#pragma unroll
    for (int k = 0; k < D; k++)
        acc = fmaf(s[k], W[k * D + j], acc);   // W[k][j]: coalesced across threads
    out2[b * D + j] = acc;
}

// ---------------------------------------------------------------------------
// Launch. Inputs (metadata order): x, eps, W_pred, b_pred, edge_index, batch.
// Output: out [N_NODES*D] followed by pooled2 [NBATCH*D].
// ---------------------------------------------------------------------------
extern "C" void kernel_launch(void* const* d_in, const int* in_sizes, int n_in,
                              void* d_out, int out_size) {
    const float* x     = (const float*)d_in[0];
    const float* eps   = (const float*)d_in[1];
    const float* Wp    = (const float*)d_in[2];
    const float* bp    = (const float*)d_in[3];
    const int*   ei    = (const int*)d_in[4];
    const int*   batch = (const int*)d_in[5];

    float* out  = (float*)d_out;
    float* out2 = out + (size_t)N_NODES * D;

    // 1) agg = (1+eps)*x; zero pooling accumulators
    {
        int total4 = N_NODES * D / 4;
        int threads = 256;
        int blocks = (total4 + threads - 1) / threads;
        k_init<<<blocks, threads>>>(x, eps);
    }

    // 2) edge scatter: one warp per edge
    {
        int threads = 256;                       // 8 warps/block
        long long totalThreads = (long long)N_EDGES * 32;
        int blocks = (int)((totalThreads + threads - 1) / threads);
        k_edges<<<blocks, threads>>>(x, ei);
    }

    // 3) relu + write out + per-batch row sums
    {
        dim3 block(128, 4);
        int blocks = (N_NODES + ROWS_PER_BLOCK - 1) / ROWS_PER_BLOCK;
        k_epilogue<<<blocks, block>>>(out, batch);
    }

    // 4) tiny pooled GEMM
    k_pool<<<NBATCH, 128>>>(Wp, bp, out2);
}